// round 1
// baseline (speedup 1.0000x reference)
#include <cuda_runtime.h>

// ---------------- problem constants ----------------
#define B_WIN 4096
#define NTOK  49
#define DIM   192
#define HEADS 6
#define HD    32
#define MTOT  (B_WIN * NTOK)            // 200704 rows
#define QKV_N (3 * DIM)                 // 576
#define SCALE 0.17677669529663687f      // 1/sqrt(32)

// ---------------- scratch (device globals: no allocs allowed) ----------------
__device__ float g_qkv [(size_t)3 * B_WIN * HEADS * NTOK * HD];   // [3,B,H,N,hd]
__device__ float g_attn[(size_t)MTOT * DIM];                      // [B,N,192]
__device__ float g_bias[HEADS * NTOK * NTOK];                     // [H,49,49]

// ---------------- helpers ----------------
__device__ __forceinline__ unsigned f2tf(float f) {
    unsigned u;
    asm("cvt.rna.tf32.f32 %0, %1;" : "=r"(u) : "f"(f));
    return u;
}

__device__ __forceinline__ void mma8(float* c, const unsigned* a, const unsigned* b) {
    asm volatile(
        "mma.sync.aligned.m16n8k8.row.col.f32.tf32.tf32.f32 "
        "{%0,%1,%2,%3},{%4,%5,%6,%7},{%8,%9},{%0,%1,%2,%3};\n"
        : "+f"(c[0]), "+f"(c[1]), "+f"(c[2]), "+f"(c[3])
        : "r"(a[0]), "r"(a[1]), "r"(a[2]), "r"(a[3]), "r"(b[0]), "r"(b[1]));
}

// ---------------- kernel 0: bias gather ----------------
__global__ void bias_kernel(const float* __restrict__ bias_table,
                            const int* __restrict__ rel_index) {
    int idx = blockIdx.x * blockDim.x + threadIdx.x;
    if (idx < HEADS * NTOK * NTOK) {
        int h  = idx / (NTOK * NTOK);
        int ij = idx - h * (NTOK * NTOK);
        g_bias[idx] = bias_table[rel_index[ij] * HEADS + h];
    }
}

// ---------------- GEMM: C[M, Ntot] = A[M,192] @ Bw[Ntot,192]^T + bias ----------------
// MODE 0: A = x, Ntot = 576, scatter into g_qkv (q scaled by SCALE)
// MODE 1: A = g_attn, Ntot = 192, write to Cout (+proj_b)
template <int MODE>
__global__ void __launch_bounds__(128) gemm_kernel(const float* __restrict__ Ain,
                                                   const float* __restrict__ Bw,
                                                   const float* __restrict__ bias,
                                                   float* __restrict__ Cout) {
    __shared__ __align__(16) unsigned As[64 * 68];
    __shared__ __align__(16) unsigned Bs[64 * 68];

    const float* A = (MODE == 0) ? Ain : g_attn;

    const int tid = threadIdx.x;
    const int m0  = blockIdx.x * 64;
    const int n0  = blockIdx.y * 64;
    const int w = tid >> 5, lane = tid & 31, g = lane >> 2, t = lane & 3;
    const int wm = (w >> 1) * 32, wn = (w & 1) * 32;

    float acc[2][4][4];
#pragma unroll
    for (int f = 0; f < 2; f++)
#pragma unroll
        for (int j = 0; j < 4; j++)
#pragma unroll
            for (int v = 0; v < 4; v++) acc[f][j][v] = 0.f;

    const int sr = tid >> 4;          // 0..7
    const int sc = (tid & 15) << 2;   // 0,4,...,60

    for (int kt = 0; kt < 3; kt++) {
        const int kb = kt * 64;
#pragma unroll
        for (int i = 0; i < 8; i++) {
            int r = sr + i * 8;
            float4 va = *reinterpret_cast<const float4*>(A + (size_t)(m0 + r) * 192 + kb + sc);
            uint4 ua; ua.x = f2tf(va.x); ua.y = f2tf(va.y); ua.z = f2tf(va.z); ua.w = f2tf(va.w);
            *reinterpret_cast<uint4*>(&As[r * 68 + sc]) = ua;
            float4 vb = *reinterpret_cast<const float4*>(Bw + (size_t)(n0 + r) * 192 + kb + sc);
            uint4 ub; ub.x = f2tf(vb.x); ub.y = f2tf(vb.y); ub.z = f2tf(vb.z); ub.w = f2tf(vb.w);
            *reinterpret_cast<uint4*>(&Bs[r * 68 + sc]) = ub;
        }
        __syncthreads();
#pragma unroll
        for (int ks = 0; ks < 8; ks++) {
            const int k0 = ks * 8;
            unsigned a[2][4], bb[4][2];
#pragma unroll
            for (int f = 0; f < 2; f++) {
                int rA = wm + f * 16 + g;
                a[f][0] = As[rA * 68 + k0 + t];
                a[f][1] = As[(rA + 8) * 68 + k0 + t];
                a[f][2] = As[rA * 68 + k0 + t + 4];
                a[f][3] = As[(rA + 8) * 68 + k0 + t + 4];
            }
#pragma unroll
            for (int j = 0; j < 4; j++) {
                int rB = wn + j * 8 + g;
                bb[j][0] = Bs[rB * 68 + k0 + t];
                bb[j][1] = Bs[rB * 68 + k0 + t + 4];
            }
#pragma unroll
            for (int f = 0; f < 2; f++)
#pragma unroll
                for (int j = 0; j < 4; j++) mma8(acc[f][j], a[f], bb[j]);
        }
        __syncthreads();
    }

    // epilogue
#pragma unroll
    for (int f = 0; f < 2; f++) {
        const int ma = m0 + wm + f * 16 + g;
        const int mb = ma + 8;
        const int ba = ma / 49, ta = ma - ba * 49;
        const int bb2 = mb / 49, tb = mb - bb2 * 49;
#pragma unroll
        for (int j = 0; j < 4; j++) {
            const int gc0 = n0 + wn + j * 8 + 2 * t;
#pragma unroll
            for (int cc = 0; cc < 2; cc++) {
                const int gc = gc0 + cc;
                float v0 = acc[f][j][cc]     + bias[gc];
                float v1 = acc[f][j][2 + cc] + bias[gc];
                if (MODE == 0) {
                    if (gc < 192) { v0 *= SCALE; v1 *= SCALE; }   // pre-scale q
                    const int s  = gc / 192;
                    const int hh = (gc - s * 192) >> 5;
                    const int d  = gc & 31;
                    g_qkv[((((size_t)s * B_WIN + ba)  * HEADS + hh) * NTOK + ta) * HD + d] = v0;
                    g_qkv[((((size_t)s * B_WIN + bb2) * HEADS + hh) * NTOK + tb) * HD + d] = v1;
                } else {
                    Cout[(size_t)ma * DIM + gc] = v0;
                    Cout[(size_t)mb * DIM + gc] = v1;
                }
            }
        }
    }
}

// ---------------- attention: one block per (window, head) ----------------
// smem layout (unsigned words):
//   [0,4608)   qs(64x36=2304) + ks(64x36=2304)  --- reused as Ps(64x68=4352)
//   [4608,7168) vs(64x40=2560)
//   [7168,9569) bias (2401 floats)
__global__ void __launch_bounds__(128) attn_kernel() {
    __shared__ __align__(16) unsigned sm[9600];
    unsigned* qs = sm;
    unsigned* ks = sm + 2304;
    unsigned* Ps = sm;             // reuse after barrier
    unsigned* vs = sm + 4608;
    float* biasf = reinterpret_cast<float*>(sm + 7168);

    const int tid = threadIdx.x;
    const int bh = blockIdx.x;
    const int b = bh / HEADS, h = bh - b * HEADS;

    const float* qg = g_qkv + (size_t)bh * (NTOK * HD);
    const float* kg = qg + (size_t)B_WIN * HEADS * NTOK * HD;
    const float* vg = kg + (size_t)B_WIN * HEADS * NTOK * HD;

    // stage q,k,v (tf32, rows >=49 zero-padded)
    for (int idx = tid; idx < 512; idx += 128) {
        const int r = idx >> 3, c4 = (idx & 7) << 2;
        float4 vq, vk, vv;
        if (r < NTOK) {
            vq = *reinterpret_cast<const float4*>(qg + r * 32 + c4);
            vk = *reinterpret_cast<const float4*>(kg + r * 32 + c4);
            vv = *reinterpret_cast<const float4*>(vg + r * 32 + c4);
        } else {
            vq = make_float4(0.f, 0.f, 0.f, 0.f); vk = vq; vv = vq;
        }
        uint4 uq; uq.x = f2tf(vq.x); uq.y = f2tf(vq.y); uq.z = f2tf(vq.z); uq.w = f2tf(vq.w);
        uint4 uk; uk.x = f2tf(vk.x); uk.y = f2tf(vk.y); uk.z = f2tf(vk.z); uk.w = f2tf(vk.w);
        uint4 uv; uv.x = f2tf(vv.x); uv.y = f2tf(vv.y); uv.z = f2tf(vv.z); uv.w = f2tf(vv.w);
        *reinterpret_cast<uint4*>(&qs[r * 36 + c4]) = uq;
        *reinterpret_cast<uint4*>(&ks[r * 36 + c4]) = uk;
        *reinterpret_cast<uint4*>(&vs[r * 40 + c4]) = uv;
    }
    for (int i = tid; i < NTOK * NTOK; i += 128) biasf[i] = g_bias[h * (NTOK * NTOK) + i];
    __syncthreads();

    const int w = tid >> 5, lane = tid & 31, g = lane >> 2, t = lane & 3;
    const int i0 = w * 16 + g, i1 = i0 + 8;

    // ---- S = q @ k^T (q already scaled) ----
    float sacc[8][4];
#pragma unroll
    for (int j = 0; j < 8; j++)
#pragma unroll
        for (int v = 0; v < 4; v++) sacc[j][v] = 0.f;

#pragma unroll
    for (int ksp = 0; ksp < 4; ksp++) {
        const int k0 = ksp * 8;
        unsigned a[4] = { qs[i0 * 36 + k0 + t], qs[i1 * 36 + k0 + t],
                          qs[i0 * 36 + k0 + t + 4], qs[i1 * 36 + k0 + t + 4] };
#pragma unroll
        for (int j = 0; j < 8; j++) {
            unsigned bb[2] = { ks[(j * 8 + g) * 36 + k0 + t],
                               ks[(j * 8 + g) * 36 + k0 + t + 4] };
            mma8(sacc[j], a, bb);
        }
    }
    __syncthreads();  // everyone done reading qs/ks before Ps overwrite

    // ---- bias + mask + softmax (register, quad-shuffle reduce) ----
    float mx0 = -1e30f, mx1 = -1e30f;
#pragma unroll
    for (int j = 0; j < 8; j++) {
        const int j0 = j * 8 + 2 * t, j1 = j0 + 1;
        sacc[j][0] = (i0 < 49 && j0 < 49) ? sacc[j][0] + biasf[i0 * 49 + j0] : -1e30f;
        sacc[j][1] = (i0 < 49 && j1 < 49) ? sacc[j][1] + biasf[i0 * 49 + j1] : -1e30f;
        sacc[j][2] = (i1 < 49 && j0 < 49) ? sacc[j][2] + biasf[i1 * 49 + j0] : -1e30f;
        sacc[j][3] = (i1 < 49 && j1 < 49) ? sacc[j][3] + biasf[i1 * 49 + j1] : -1e30f;
        mx0 = fmaxf(mx0, fmaxf(sacc[j][0], sacc[j][1]));
        mx1 = fmaxf(mx1, fmaxf(sacc[j][2], sacc[j][3]));
    }
    mx0 = fmaxf(mx0, __shfl_xor_sync(0xffffffffu, mx0, 1));
    mx0 = fmaxf(mx0, __shfl_xor_sync(0xffffffffu, mx0, 2));
    mx1 = fmaxf(mx1, __shfl_xor_sync(0xffffffffu, mx1, 1));
    mx1 = fmaxf(mx1, __shfl_xor_sync(0xffffffffu, mx1, 2));

    float s0 = 0.f, s1 = 0.f;
#pragma unroll
    for (int j = 0; j < 8; j++) {
        float p0 = __expf(sacc[j][0] - mx0); sacc[j][0] = p0; s0 += p0;
        float p1 = __expf(sacc[j][1] - mx0); sacc[j][1] = p1; s0 += p1;
        float p2 = __expf(sacc[j][2] - mx1); sacc[j][2] = p2; s1 += p2;
        float p3 = __expf(sacc[j][3] - mx1); sacc[j][3] = p3; s1 += p3;
    }
    s0 += __shfl_xor_sync(0xffffffffu, s0, 1);
    s0 += __shfl_xor_sync(0xffffffffu, s0, 2);
    s1 += __shfl_xor_sync(0xffffffffu, s1, 1);
    s1 += __shfl_xor_sync(0xffffffffu, s1, 2);

    // store unnormalized P (tf32) to smem (each warp writes only its own 16 rows)
#pragma unroll
    for (int j = 0; j < 8; j++) {
        const int j0 = j * 8 + 2 * t;
        Ps[i0 * 68 + j0]     = f2tf(sacc[j][0]);
        Ps[i0 * 68 + j0 + 1] = f2tf(sacc[j][1]);
        Ps[i1 * 68 + j0]     = f2tf(sacc[j][2]);
        Ps[i1 * 68 + j0 + 1] = f2tf(sacc[j][3]);
    }
    __syncwarp();

    // ---- O = P @ V ----
    float oacc[4][4];
#pragma unroll
    for (int nb = 0; nb < 4; nb++)
#pragma unroll
        for (int v = 0; v < 4; v++) oacc[nb][v] = 0.f;

#pragma unroll
    for (int ksp = 0; ksp < 8; ksp++) {
        const int k0 = ksp * 8;
        unsigned a[4] = { Ps[i0 * 68 + k0 + t], Ps[i1 * 68 + k0 + t],
                          Ps[i0 * 68 + k0 + t + 4], Ps[i1 * 68 + k0 + t + 4] };
#pragma unroll
        for (int nb = 0; nb < 4; nb++) {
            unsigned bb[2] = { vs[(k0 + t) * 40 + nb * 8 + g],
                               vs[(k0 + t + 4) * 40 + nb * 8 + g] };
            mma8(oacc[nb], a, bb);
        }
    }

    const float inv0 = 1.f / s0, inv1 = 1.f / s1;
    if (i0 < 49) {
        const size_t base = ((size_t)b * 49 + i0) * 192 + h * 32;
#pragma unroll
        for (int nb = 0; nb < 4; nb++) {
            const int d0 = nb * 8 + 2 * t;
            g_attn[base + d0]     = oacc[nb][0] * inv0;
            g_attn[base + d0 + 1] = oacc[nb][1] * inv0;
        }
    }
    if (i1 < 49) {
        const size_t base = ((size_t)b * 49 + i1) * 192 + h * 32;
#pragma unroll
        for (int nb = 0; nb < 4; nb++) {
            const int d0 = nb * 8 + 2 * t;
            g_attn[base + d0]     = oacc[nb][2] * inv1;
            g_attn[base + d0 + 1] = oacc[nb][3] * inv1;
        }
    }
}

// ---------------- launch ----------------
extern "C" void kernel_launch(void* const* d_in, const int* in_sizes, int n_in,
                              void* d_out, int out_size) {
    const float* x          = (const float*)d_in[0];
    const float* qkv_w      = (const float*)d_in[1];
    const float* qkv_b      = (const float*)d_in[2];
    const float* proj_w     = (const float*)d_in[3];
    const float* proj_b     = (const float*)d_in[4];
    const float* bias_table = (const float*)d_in[5];
    const int*   rel_index  = (const int*)d_in[6];
    float* out = (float*)d_out;

    bias_kernel<<<(HEADS * NTOK * NTOK + 255) / 256, 256>>>(bias_table, rel_index);
    gemm_kernel<0><<<dim3(MTOT / 64, QKV_N / 64), 128>>>(x, qkv_w, qkv_b, nullptr);
    attn_kernel<<<B_WIN * HEADS, 128>>>();
    gemm_kernel<1><<<dim3(MTOT / 64, DIM / 64), 128>>>(nullptr, proj_w, proj_b, out);
}

// round 2
// speedup vs baseline: 1.8635x; 1.8635x over previous
#include <cuda_runtime.h>
#include <cuda_fp16.h>

// ---------------- problem constants ----------------
#define B_WIN 4096
#define NTOK  49
#define DIM   192
#define HEADS 6
#define HD    32
#define MTOT  (B_WIN * NTOK)            // 200704 rows
#define QKV_N (3 * DIM)                 // 576
#define SCALE 0.17677669529663687f      // 1/sqrt(32)

// ---------------- scratch (device globals: no allocs allowed) ----------------
__device__ __half g_qkvh[(size_t)3 * B_WIN * HEADS * NTOK * HD];  // [3,B,H,49,32] half
__device__ __half g_attnh[(size_t)MTOT * DIM];                    // [B*49,192] half
__device__ float  g_bias[HEADS * NTOK * NTOK];                    // [H,49,49]

// ---------------- helpers ----------------
__device__ __forceinline__ unsigned packh2(float a, float b) {
    __half2 h = __floats2half2_rn(a, b);   // low = a, high = b
    return *reinterpret_cast<unsigned*>(&h);
}

__device__ __forceinline__ void mma16(float* c, const unsigned* a, const unsigned* b) {
    asm volatile(
        "mma.sync.aligned.m16n8k16.row.col.f32.f16.f16.f32 "
        "{%0,%1,%2,%3},{%4,%5,%6,%7},{%8,%9},{%0,%1,%2,%3};\n"
        : "+f"(c[0]), "+f"(c[1]), "+f"(c[2]), "+f"(c[3])
        : "r"(a[0]), "r"(a[1]), "r"(a[2]), "r"(a[3]), "r"(b[0]), "r"(b[1]));
}

// ---------------- kernel 0: bias gather ----------------
__global__ void bias_kernel(const float* __restrict__ bias_table,
                            const int* __restrict__ rel_index) {
    int idx = blockIdx.x * blockDim.x + threadIdx.x;
    if (idx < HEADS * NTOK * NTOK) {
        int h  = idx / (NTOK * NTOK);
        int ij = idx - h * (NTOK * NTOK);
        g_bias[idx] = bias_table[rel_index[ij] * HEADS + h];
    }
}

// ---------------- GEMM: C[M, Ntot] = A[M,192] @ W[Ntot,192]^T + bias ----------------
// block tile 128x64, 4 warps (2x2), warp tile 64x32, k-tile 64, fp16 mma.
// MODE 0: A = x (fp32), scatter half into g_qkvh (q pre-scaled)
// MODE 1: A = g_attnh (half), write fp32 to Cout (+proj_b)
template <int MODE>
__global__ void __launch_bounds__(128) gemm_kernel(const float* __restrict__ Ain,
                                                   const float* __restrict__ Bw,
                                                   const float* __restrict__ bias,
                                                   float* __restrict__ Cout) {
    __shared__ __align__(16) unsigned As[128 * 36];   // 128 rows x 64 halves (stride 36 words)
    __shared__ __align__(16) unsigned Bs[64 * 36];    // 64 cols  x 64 halves

    const int tid = threadIdx.x;
    const int w = tid >> 5, lane = tid & 31, g = lane >> 2, t = lane & 3;
    const int wm = (w >> 1) * 64, wn = (w & 1) * 32;
    const int m0 = blockIdx.y * 128;
    const int n0 = blockIdx.x * 64;
    const int ty = tid >> 4;            // 0..7
    const int tx = tid & 15;            // 0..15

    float acc[4][4][4];
#pragma unroll
    for (int mf = 0; mf < 4; mf++)
#pragma unroll
        for (int nf = 0; nf < 4; nf++)
#pragma unroll
            for (int v = 0; v < 4; v++) acc[mf][nf][v] = 0.f;

    for (int kt = 0; kt < 3; kt++) {
        const int kb = kt * 64;
        // ---- stage A ----
        if (MODE == 0) {
#pragma unroll
            for (int i = 0; i < 16; i++) {
                const int r = ty + i * 8;
                float4 v = *reinterpret_cast<const float4*>(Ain + (size_t)(m0 + r) * 192 + kb + tx * 4);
                uint2 u; u.x = packh2(v.x, v.y); u.y = packh2(v.z, v.w);
                *reinterpret_cast<uint2*>(&As[r * 36 + tx * 2]) = u;
            }
        } else {
#pragma unroll
            for (int i = 0; i < 16; i++) {
                const int r = ty + i * 8;
                uint2 u = *reinterpret_cast<const uint2*>(g_attnh + (size_t)(m0 + r) * 192 + kb + tx * 4);
                *reinterpret_cast<uint2*>(&As[r * 36 + tx * 2]) = u;
            }
        }
        // ---- stage B (weights, fp32) ----
#pragma unroll
        for (int i = 0; i < 8; i++) {
            const int r = ty + i * 8;
            float4 v = *reinterpret_cast<const float4*>(Bw + (size_t)(n0 + r) * 192 + kb + tx * 4);
            uint2 u; u.x = packh2(v.x, v.y); u.y = packh2(v.z, v.w);
            *reinterpret_cast<uint2*>(&Bs[r * 36 + tx * 2]) = u;
        }
        __syncthreads();

        // ---- mainloop: 4 k16 steps ----
#pragma unroll
        for (int ks = 0; ks < 4; ks++) {
            const int kw = ks * 8;
            unsigned a[4][4], bf[4][2];
#pragma unroll
            for (int mf = 0; mf < 4; mf++) {
                const int base = (wm + mf * 16 + g) * 36 + kw + t;
                a[mf][0] = As[base];
                a[mf][1] = As[base + 8 * 36];
                a[mf][2] = As[base + 4];
                a[mf][3] = As[base + 8 * 36 + 4];
            }
#pragma unroll
            for (int nf = 0; nf < 4; nf++) {
                const int base = (wn + nf * 8 + g) * 36 + kw + t;
                bf[nf][0] = Bs[base];
                bf[nf][1] = Bs[base + 4];
            }
#pragma unroll
            for (int mf = 0; mf < 4; mf++)
#pragma unroll
                for (int nf = 0; nf < 4; nf++) mma16(acc[mf][nf], a[mf], bf[nf]);
        }
        __syncthreads();
    }

    // ---- epilogue ----
#pragma unroll
    for (int mf = 0; mf < 4; mf++) {
        const int ma = m0 + wm + mf * 16 + g;
        const int mb = ma + 8;
        const int wa = ma / 49, ta = ma - wa * 49;
        const int wb = mb / 49, tb = mb - wb * 49;
#pragma unroll
        for (int nf = 0; nf < 4; nf++) {
            const int gc = n0 + wn + nf * 8 + 2 * t;
            float v00 = acc[mf][nf][0] + bias[gc];
            float v01 = acc[mf][nf][1] + bias[gc + 1];
            float v10 = acc[mf][nf][2] + bias[gc];
            float v11 = acc[mf][nf][3] + bias[gc + 1];
            if (MODE == 0) {
                if (gc < 192) { v00 *= SCALE; v01 *= SCALE; v10 *= SCALE; v11 *= SCALE; }
                const int s  = gc / 192;
                const int hh = (gc - s * 192) >> 5;
                const int d  = gc & 31;
                __half2* pa = reinterpret_cast<__half2*>(
                    g_qkvh + ((((size_t)s * B_WIN + wa) * HEADS + hh) * NTOK + ta) * HD + d);
                __half2* pb = reinterpret_cast<__half2*>(
                    g_qkvh + ((((size_t)s * B_WIN + wb) * HEADS + hh) * NTOK + tb) * HD + d);
                *pa = __floats2half2_rn(v00, v01);
                *pb = __floats2half2_rn(v10, v11);
            } else {
                *reinterpret_cast<float2*>(Cout + (size_t)ma * DIM + gc) = make_float2(v00, v01);
                *reinterpret_cast<float2*>(Cout + (size_t)mb * DIM + gc) = make_float2(v10, v11);
            }
        }
    }
}

// ---------------- attention: one block per (window, head), fp16 mma ----------------
// smem words: qs 64x20=1280 | ks 1280 | vs 32x36=1152 | bias 2401 fp32
// Ps (64x36=2304) reuses the qs/ks region after S is computed.
__global__ void __launch_bounds__(128) attn_kernel() {
    __shared__ __align__(16) unsigned sm[6144];
    unsigned* qs = sm;
    unsigned* ks = sm + 1280;
    unsigned* vs = sm + 2560;
    unsigned* Ps = sm;
    float* biasf = reinterpret_cast<float*>(sm + 3712);

    const int tid = threadIdx.x;
    const int bh = blockIdx.x;
    const int b = bh / HEADS, h = bh - b * HEADS;

    const __half* qg = g_qkvh + (size_t)bh * (NTOK * HD);
    const __half* kg = qg + (size_t)B_WIN * HEADS * NTOK * HD;
    const __half* vg = kg + (size_t)B_WIN * HEADS * NTOK * HD;

    // stage q,k row-major (half, zero-pad rows >=49); v transposed [dim][token]
    for (int idx = tid; idx < 512; idx += 128) {
        const int r = idx >> 3, c = idx & 7;   // c: group of 4 halves
        uint2 zq = make_uint2(0u, 0u), zk = zq, zv = zq;
        if (r < NTOK) {
            zq = *reinterpret_cast<const uint2*>(qg + r * 32 + c * 4);
            zk = *reinterpret_cast<const uint2*>(kg + r * 32 + c * 4);
            zv = *reinterpret_cast<const uint2*>(vg + r * 32 + c * 4);
        }
        *reinterpret_cast<uint2*>(&qs[r * 20 + c * 2]) = zq;
        *reinterpret_cast<uint2*>(&ks[r * 20 + c * 2]) = zk;
        // transpose v: halves are dims d0..d0+3 of token r -> vs[dim][token]
        const __half* hv = reinterpret_cast<const __half*>(&zv);
        char* vbase = reinterpret_cast<char*>(vs);
#pragma unroll
        for (int u = 0; u < 4; u++) {
            const int d = c * 4 + u;
            *reinterpret_cast<__half*>(vbase + (d * 36 + (r >> 1)) * 4 + (r & 1) * 2) = hv[u];
        }
    }
    for (int i = tid; i < NTOK * NTOK; i += 128) biasf[i] = g_bias[h * (NTOK * NTOK) + i];
    __syncthreads();

    const int w = tid >> 5, lane = tid & 31, g = lane >> 2, t = lane & 3;
    const int i0 = w * 16 + g, i1 = i0 + 8;

    // ---- S = q @ k^T (K = 32 -> 2 fp16 k-steps) ----
    float sacc[8][4];
#pragma unroll
    for (int j = 0; j < 8; j++)
#pragma unroll
        for (int v = 0; v < 4; v++) sacc[j][v] = 0.f;

#pragma unroll
    for (int ks2 = 0; ks2 < 2; ks2++) {
        const int kw = ks2 * 8;
        unsigned a[4] = { qs[i0 * 20 + kw + t], qs[i1 * 20 + kw + t],
                          qs[i0 * 20 + kw + t + 4], qs[i1 * 20 + kw + t + 4] };
#pragma unroll
        for (int j = 0; j < 8; j++) {
            unsigned bf[2] = { ks[(j * 8 + g) * 20 + kw + t],
                               ks[(j * 8 + g) * 20 + kw + t + 4] };
            mma16(sacc[j], a, bf);
        }
    }
    __syncthreads();   // done reading qs/ks before Ps overwrite

    // ---- bias + mask + softmax ----
    float mx0 = -1e30f, mx1 = -1e30f;
#pragma unroll
    for (int j = 0; j < 8; j++) {
        const int j0 = j * 8 + 2 * t, j1 = j0 + 1;
        sacc[j][0] = (i0 < 49 && j0 < 49) ? sacc[j][0] + biasf[i0 * 49 + j0] : -1e30f;
        sacc[j][1] = (i0 < 49 && j1 < 49) ? sacc[j][1] + biasf[i0 * 49 + j1] : -1e30f;
        sacc[j][2] = (i1 < 49 && j0 < 49) ? sacc[j][2] + biasf[i1 * 49 + j0] : -1e30f;
        sacc[j][3] = (i1 < 49 && j1 < 49) ? sacc[j][3] + biasf[i1 * 49 + j1] : -1e30f;
        mx0 = fmaxf(mx0, fmaxf(sacc[j][0], sacc[j][1]));
        mx1 = fmaxf(mx1, fmaxf(sacc[j][2], sacc[j][3]));
    }
    mx0 = fmaxf(mx0, __shfl_xor_sync(0xffffffffu, mx0, 1));
    mx0 = fmaxf(mx0, __shfl_xor_sync(0xffffffffu, mx0, 2));
    mx1 = fmaxf(mx1, __shfl_xor_sync(0xffffffffu, mx1, 1));
    mx1 = fmaxf(mx1, __shfl_xor_sync(0xffffffffu, mx1, 2));

    float s0 = 0.f, s1 = 0.f;
#pragma unroll
    for (int j = 0; j < 8; j++) {
        float p0 = __expf(sacc[j][0] - mx0); sacc[j][0] = p0; s0 += p0;
        float p1 = __expf(sacc[j][1] - mx0); sacc[j][1] = p1; s0 += p1;
        float p2 = __expf(sacc[j][2] - mx1); sacc[j][2] = p2; s1 += p2;
        float p3 = __expf(sacc[j][3] - mx1); sacc[j][3] = p3; s1 += p3;
    }
    s0 += __shfl_xor_sync(0xffffffffu, s0, 1);
    s0 += __shfl_xor_sync(0xffffffffu, s0, 2);
    s1 += __shfl_xor_sync(0xffffffffu, s1, 1);
    s1 += __shfl_xor_sync(0xffffffffu, s1, 2);

    // store unnormalized P as half2 (own rows only)
#pragma unroll
    for (int j = 0; j < 8; j++) {
        Ps[i0 * 36 + j * 4 + t] = packh2(sacc[j][0], sacc[j][1]);
        Ps[i1 * 36 + j * 4 + t] = packh2(sacc[j][2], sacc[j][3]);
    }
    __syncwarp();

    // ---- O = P @ V (K = 64 tokens -> 4 k-steps, N = 32 dims) ----
    float oacc[4][4];
#pragma unroll
    for (int nb = 0; nb < 4; nb++)
#pragma unroll
        for (int v = 0; v < 4; v++) oacc[nb][v] = 0.f;

#pragma unroll
    for (int kk = 0; kk < 4; kk++) {
        const int kw = kk * 8;
        unsigned a[4] = { Ps[i0 * 36 + kw + t], Ps[i1 * 36 + kw + t],
                          Ps[i0 * 36 + kw + t + 4], Ps[i1 * 36 + kw + t + 4] };
#pragma unroll
        for (int nb = 0; nb < 4; nb++) {
            unsigned bf[2] = { vs[(nb * 8 + g) * 36 + kw + t],
                               vs[(nb * 8 + g) * 36 + kw + t + 4] };
            mma16(oacc[nb], a, bf);
        }
    }

    const float inv0 = 1.f / s0, inv1 = 1.f / s1;
    if (i0 < 49) {
        __half* base = g_attnh + ((size_t)b * 49 + i0) * 192 + h * 32;
#pragma unroll
        for (int nb = 0; nb < 4; nb++) {
            const int d0 = nb * 8 + 2 * t;
            *reinterpret_cast<__half2*>(base + d0) =
                __floats2half2_rn(oacc[nb][0] * inv0, oacc[nb][1] * inv0);
        }
    }
    if (i1 < 49) {
        __half* base = g_attnh + ((size_t)b * 49 + i1) * 192 + h * 32;
#pragma unroll
        for (int nb = 0; nb < 4; nb++) {
            const int d0 = nb * 8 + 2 * t;
            *reinterpret_cast<__half2*>(base + d0) =
                __floats2half2_rn(oacc[nb][2] * inv1, oacc[nb][3] * inv1);
        }
    }
}

// ---------------- launch ----------------
extern "C" void kernel_launch(void* const* d_in, const int* in_sizes, int n_in,
                              void* d_out, int out_size) {
    const float* x          = (const float*)d_in[0];
    const float* qkv_w      = (const float*)d_in[1];
    const float* qkv_b      = (const float*)d_in[2];
    const float* proj_w     = (const float*)d_in[3];
    const float* proj_b     = (const float*)d_in[4];
    const float* bias_table = (const float*)d_in[5];
    const int*   rel_index  = (const int*)d_in[6];
    float* out = (float*)d_out;

    bias_kernel<<<(HEADS * NTOK * NTOK + 255) / 256, 256>>>(bias_table, rel_index);
    gemm_kernel<0><<<dim3(QKV_N / 64, MTOT / 128), 128>>>(x, qkv_w, qkv_b, nullptr);
    attn_kernel<<<B_WIN * HEADS, 128>>>();
    gemm_kernel<1><<<dim3(DIM / 64, MTOT / 128), 128>>>(x, proj_w, proj_b, out);
}